// round 4
// baseline (speedup 1.0000x reference)
#include <cuda_runtime.h>

// ---------------- problem constants (static per reference) ----------------
#define EMBED 256
#define NH    8
#define NL    3
#define NP    4
#define HD    32          // EMBED/NH
#define BATCH 4
#define NQ    300
#define NK    17
#define LQ    (NQ*NK)     // 5100
#define M2    (BATCH*LQ)  // 20400 query rows
#define LVAL  13125       // 100*100 + 50*50 + 25*25
#define MV    (BATCH*LVAL)// 52500 value rows

// ---------------- scratch (device globals: no allocation allowed) ---------
__device__ float g_v  [(size_t)MV * EMBED];           // projected value  (53.8 MB)
__device__ float g_off[(size_t)M2 * NH*NL*NP*4];      // sampling offsets (31.3 MB)
__device__ float g_aw [(size_t)M2 * NH*NL*NP];        // attn weights     ( 7.8 MB)
__device__ float g_tmp[(size_t)M2 * EMBED];           // aggregated heads (20.9 MB)

// ---------------- packed f32x2 helpers (FFMA2 path, PTX-only) -------------
static __device__ __forceinline__ unsigned long long pk2(float lo, float hi) {
    unsigned long long r;
    asm("mov.b64 %0, {%1,%2};" : "=l"(r) : "f"(lo), "f"(hi));
    return r;
}
static __device__ __forceinline__ void upk2(unsigned long long v, float& lo, float& hi) {
    asm("mov.b64 {%0,%1}, %2;" : "=f"(lo), "=f"(hi) : "l"(v));
}
static __device__ __forceinline__ void fma2(unsigned long long& d,
                                            unsigned long long a,
                                            unsigned long long b) {
    asm("fma.rn.f32x2 %0, %1, %2, %0;" : "+l"(d) : "l"(a), "l"(b));
}

// ---------------- GEMM: C[M,N] = A[M,K] @ W[N,K]^T + bias (opt. row mask) -
// 128x128 tile, BK=16, 256 threads, each thread 8x8 via 8x4 f32x2 accum.
template <bool MASKED>
__global__ __launch_bounds__(256, 2)
void gemm_tn(const float* __restrict__ A, const float* __restrict__ W,
             const float* __restrict__ bias, const unsigned char* __restrict__ mask,
             float* __restrict__ C, int M, int N, int K)
{
    const int BM = 128, BN = 128, BK = 16;
    __shared__ __align__(16) float As[BK][BM + 4];
    __shared__ __align__(16) float Bs[BK][BN + 4];

    const int tid = threadIdx.x;
    const int tx  = tid & 15;          // 16 col groups of 8
    const int ty  = tid >> 4;          // 16 row groups of 8
    const int m0  = blockIdx.y * BM;
    const int n0  = blockIdx.x * BN;

    unsigned long long acc[8][4];
#pragma unroll
    for (int i = 0; i < 8; i++)
#pragma unroll
        for (int j = 0; j < 4; j++) acc[i][j] = pk2(0.f, 0.f);

    for (int k0 = 0; k0 < K; k0 += BK) {
        // load A tile (coalesced float4 along K), store transposed As[k][m]
#pragma unroll
        for (int i = 0; i < 2; i++) {
            int idx = i * 256 + tid;
            int m   = idx >> 2;
            int k4  = (idx & 3) * 4;
            float4 va = make_float4(0.f, 0.f, 0.f, 0.f);
            if (m0 + m < M)
                va = *reinterpret_cast<const float4*>(A + (size_t)(m0 + m) * K + k0 + k4);
            As[k4 + 0][m] = va.x; As[k4 + 1][m] = va.y;
            As[k4 + 2][m] = va.z; As[k4 + 3][m] = va.w;
        }
        // load W tile (W is [N,K] row-major) -> Bs[k][n]
#pragma unroll
        for (int i = 0; i < 2; i++) {
            int idx = i * 256 + tid;
            int n   = idx >> 2;
            int k4  = (idx & 3) * 4;
            float4 vb = make_float4(0.f, 0.f, 0.f, 0.f);
            if (n0 + n < N)
                vb = *reinterpret_cast<const float4*>(W + (size_t)(n0 + n) * K + k0 + k4);
            Bs[k4 + 0][n] = vb.x; Bs[k4 + 1][n] = vb.y;
            Bs[k4 + 2][n] = vb.z; Bs[k4 + 3][n] = vb.w;
        }
        __syncthreads();

#pragma unroll
        for (int k = 0; k < BK; k++) {
            float4 a0 = *reinterpret_cast<const float4*>(&As[k][ty * 8]);
            float4 a1 = *reinterpret_cast<const float4*>(&As[k][ty * 8 + 4]);
            ulonglong2 bq0 = *reinterpret_cast<const ulonglong2*>(&Bs[k][tx * 8]);
            ulonglong2 bq1 = *reinterpret_cast<const ulonglong2*>(&Bs[k][tx * 8 + 4]);
            float av[8] = {a0.x, a0.y, a0.z, a0.w, a1.x, a1.y, a1.z, a1.w};
            unsigned long long bv[4] = {bq0.x, bq0.y, bq1.x, bq1.y};
#pragma unroll
            for (int i = 0; i < 8; i++) {
                unsigned long long aa = pk2(av[i], av[i]);
#pragma unroll
                for (int j = 0; j < 4; j++) fma2(acc[i][j], aa, bv[j]);
            }
        }
        __syncthreads();
    }

    // epilogue: bias add (+ optional row-mask zeroing), guarded store
#pragma unroll
    for (int i = 0; i < 8; i++) {
        int row = m0 + ty * 8 + i;
        if (row >= M) continue;
        float vals[8];
#pragma unroll
        for (int j = 0; j < 4; j++) upk2(acc[i][j], vals[2 * j], vals[2 * j + 1]);
        bool zero = false;
        if (MASKED) zero = (mask[row] != 0);
#pragma unroll
        for (int j = 0; j < 8; j++) {
            int col = n0 + tx * 8 + j;
            if (col < N)
                C[(size_t)row * N + col] = zero ? 0.f : (vals[j] + bias[col]);
        }
    }
}

// ---------------- softmax over the 12 (NL*NP) logits per (row, head) ------
__global__ void softmax12(float* __restrict__ aw)
{
    int t = blockIdx.x * blockDim.x + threadIdx.x;
    if (t >= M2 * NH) return;
    float* p = aw + (size_t)t * 12;   // layout: row*96 + h*12, contiguous 12
    float v[12];
    float m = -1e30f;
#pragma unroll
    for (int i = 0; i < 12; i++) { v[i] = p[i]; m = fmaxf(m, v[i]); }
    float s = 0.f;
#pragma unroll
    for (int i = 0; i < 12; i++) { v[i] = __expf(v[i] - m); s += v[i]; }
    float inv = 1.f / s;
#pragma unroll
    for (int i = 0; i < 12; i++) p[i] = v[i] * inv;
}

// ---------------- deformable bilinear sampling + weighted aggregation -----
// One warp per (b, q, h); lane = head-dim channel. Each bilinear tap is a
// single coalesced 128B warp transaction into L2-resident g_v.
__global__ __launch_bounds__(256)
void sample_kernel(const float* __restrict__ refl, const float* __restrict__ refr,
                   float* __restrict__ tmp)
{
    int w    = (blockIdx.x * blockDim.x + threadIdx.x) >> 5;
    int lane = threadIdx.x & 31;
    if (w >= M2 * NH) return;
    int h   = w & (NH - 1);
    int row = w >> 3;
    int bb  = row / LQ;
    int q   = row % LQ;
    int qn  = q / NK, kk = q % NK;

    const float* offp = g_off + (size_t)row * (NH * NL * NP * 4) + h * (NL * NP * 4);
    const float* awp  = g_aw  + (size_t)row * (NH * NL * NP)     + h * (NL * NP);

    const int lvl_start[3] = {0, 10000, 12500};
    const int lvl_H[3]     = {100, 50, 25};
    const int lvl_W[3]     = {100, 50, 25};

    float acc = 0.f;
#pragma unroll
    for (int l = 0; l < NL; l++) {
        const int Hl = lvl_H[l], Wl = lvl_W[l];
        const float fW = (float)Wl, fH = (float)Hl;
        size_t ridx = ((((size_t)bb * NQ + qn) * NL + l) * NK + kk) * 2;
        float rlx = refl[ridx], rly = refl[ridx + 1];
        float rrx = refr[ridx], rry = refr[ridx + 1];
        const float* vbase = g_v + ((size_t)bb * LVAL + lvl_start[l]) * EMBED + h * HD + lane;
#pragma unroll
        for (int p2 = 0; p2 < 8; p2++) {
            int  p     = p2 & 3;
            bool right = p2 >= 4;
            float ox = offp[l * 16 + p * 4 + (right ? 2 : 0)];
            float oy = offp[l * 16 + p * 4 + (right ? 3 : 1)];
            float locx = (right ? rrx : rlx) + ox / fW;
            float locy = (right ? rry : rly) + oy / fH;
            float wgt  = awp[l * 4 + p];

            float x = locx * fW - 0.5f;
            float y = locy * fH - 0.5f;
            float x0f = floorf(x), y0f = floorf(y);
            float txf = x - x0f, tyf = y - y0f;
            int x0 = (int)x0f, y0 = (int)y0f;
            int x1 = x0 + 1,   y1 = y0 + 1;
            bool vx0 = (x0 >= 0) & (x0 < Wl), vx1 = (x1 >= 0) & (x1 < Wl);
            bool vy0 = (y0 >= 0) & (y0 < Hl), vy1 = (y1 >= 0) & (y1 < Hl);
            int cx0 = min(max(x0, 0), Wl - 1), cx1 = min(max(x1, 0), Wl - 1);
            int cy0 = min(max(y0, 0), Hl - 1), cy1 = min(max(y1, 0), Hl - 1);

            float v00 = (vx0 && vy0) ? vbase[(size_t)(cy0 * Wl + cx0) * EMBED] : 0.f;
            float v01 = (vx1 && vy0) ? vbase[(size_t)(cy0 * Wl + cx1) * EMBED] : 0.f;
            float v10 = (vx0 && vy1) ? vbase[(size_t)(cy1 * Wl + cx0) * EMBED] : 0.f;
            float v11 = (vx1 && vy1) ? vbase[(size_t)(cy1 * Wl + cx1) * EMBED] : 0.f;

            float s = (1.f - tyf) * ((1.f - txf) * v00 + txf * v01)
                    +         tyf * ((1.f - txf) * v10 + txf * v11);
            acc += wgt * s;
        }
    }
    tmp[(size_t)row * EMBED + h * HD + lane] = acc;
}

// ---------------- launch -----------------------------------------------
extern "C" void kernel_launch(void* const* d_in, const int* in_sizes, int n_in,
                              void* d_out, int out_size)
{
    const float*         query  = (const float*)d_in[0];
    const float*         refl   = (const float*)d_in[1];
    const float*         refr   = (const float*)d_in[2];
    const float*         value  = (const float*)d_in[3];
    /* d_in[4] = value_spatial_shapes: static, hardcoded */
    const unsigned char* mask   = (const unsigned char*)d_in[5];
    const float*         W_off  = (const float*)d_in[6];
    const float*         b_off  = (const float*)d_in[7];
    const float*         W_attn = (const float*)d_in[8];
    const float*         b_attn = (const float*)d_in[9];
    const float*         W_val  = (const float*)d_in[10];
    const float*         b_val  = (const float*)d_in[11];
    const float*         W_out  = (const float*)d_in[12];
    const float*         b_out  = (const float*)d_in[13];
    float*               out    = (float*)d_out;

    float *v, *off, *aw, *tmp;
    cudaGetSymbolAddress((void**)&v,   g_v);
    cudaGetSymbolAddress((void**)&off, g_off);
    cudaGetSymbolAddress((void**)&aw,  g_aw);
    cudaGetSymbolAddress((void**)&tmp, g_tmp);

    // 1. value projection + mask:  [52500,512] x [256,512]^T
    {
        dim3 grid((EMBED + 127) / 128, (MV + 127) / 128);
        gemm_tn<true><<<grid, 256>>>(value, W_val, b_val, mask, v, MV, EMBED, 2 * EMBED);
    }
    // 2a. sampling offsets: [20400,256] x [384,256]^T
    {
        dim3 grid((384 + 127) / 128, (M2 + 127) / 128);
        gemm_tn<false><<<grid, 256>>>(query, W_off, b_off, nullptr, off, M2, 384, EMBED);
    }
    // 2b. attention logits: [20400,256] x [96,256]^T
    {
        dim3 grid((96 + 127) / 128, (M2 + 127) / 128);
        gemm_tn<false><<<grid, 256>>>(query, W_attn, b_attn, nullptr, aw, M2, 96, EMBED);
    }
    // 2c. softmax over 12 per (row, head)
    softmax12<<<(M2 * NH + 255) / 256, 256>>>(aw);

    // 3. deformable sampling: one warp per (b,q,h), 8 warps/block
    sample_kernel<<<M2, 256>>>(refl, refr, tmp);

    // 4. output projection: [20400,256] x [256,256]^T
    {
        dim3 grid((EMBED + 127) / 128, (M2 + 127) / 128);
        gemm_tn<false><<<grid, 256>>>(tmp, W_out, b_out, nullptr, out, M2, EMBED, EMBED);
    }
}